// round 13
// baseline (speedup 1.0000x reference)
#include <cuda_runtime.h>
#include <cuda_bf16.h>
#include <cstdint>

// out = ((3x+1)/4)^2 ; t = fma(0.75, x, 0.25), out = t*t
// 64M fp32, HBM-streaming at the controller ceiling (~6.45 TB/s measured,
// invariant across unroll 2/4/8, 256/512-thread CTAs, cache-hint variants).
// Persistent grid-stride: one wave of resident CTAs (GB300: 152 SMs x 4 CTAs
// x 256 thr), 4x float4 front-batched per iteration.

__global__ __launch_bounds__(256, 4) void ewise_sq_persist_kernel(
    const float4* __restrict__ in, float4* __restrict__ out, unsigned n4)
{
    const unsigned tile = gridDim.x * 256u * 4u;       // float4 per full pass
    unsigned base = blockIdx.x * (256u * 4u) + threadIdx.x;

    #define EW(dst, src) do {                       \
        float t0 = fmaf(0.75f, (src).x, 0.25f);     \
        float t1 = fmaf(0.75f, (src).y, 0.25f);     \
        float t2 = fmaf(0.75f, (src).z, 0.25f);     \
        float t3 = fmaf(0.75f, (src).w, 0.25f);     \
        (dst).x = t0 * t0; (dst).y = t1 * t1;       \
        (dst).z = t2 * t2; (dst).w = t3 * t3;       \
    } while (0)

    // Full 4-group iterations (max index of the group is base + 768).
    while (base + 768u < n4) {
        float4 a0 = __ldcg(&in[base]);
        float4 a1 = __ldcg(&in[base + 256u]);
        float4 a2 = __ldcg(&in[base + 512u]);
        float4 a3 = __ldcg(&in[base + 768u]);

        float4 r0, r1, r2, r3;
        EW(r0, a0); EW(r1, a1); EW(r2, a2); EW(r3, a3);

        __stcs(&out[base],        r0);
        __stcs(&out[base + 256u], r1);
        __stcs(&out[base + 512u], r2);
        __stcs(&out[base + 768u], r3);
        base += tile;
    }

    // Tail: remaining in-bounds lanes (empty when n4 % tile == 0).
    for (unsigned k = 0; k < 4u; k++) {
        unsigned i = base + k * 256u;
        if (i < n4) {
            float4 a = __ldcg(&in[i]);
            float4 r;
            EW(r, a);
            __stcs(&out[i], r);
        }
    }
    #undef EW
}

// Scalar tail for element counts not divisible by 4 (not hit for 8192x8192).
__global__ void ewise_sq_scalar_tail(const float* __restrict__ in,
                                     float* __restrict__ out,
                                     unsigned start, unsigned n)
{
    unsigned i = start + blockIdx.x * blockDim.x + threadIdx.x;
    if (i < n) {
        float t = fmaf(0.75f, in[i], 0.25f);
        out[i] = t * t;
    }
}

extern "C" void kernel_launch(void* const* d_in, const int* in_sizes, int n_in,
                              void* d_out, int out_size)
{
    const float* x = (const float*)d_in[0];
    float* y = (float*)d_out;
    unsigned n = (unsigned)in_sizes[0];   // 67108864
    unsigned n4 = n >> 2;                 // 16777216 float4

    const unsigned blocks = 152u * 4u;    // one resident wave (GB300: 152 SMs)
    ewise_sq_persist_kernel<<<blocks, 256>>>((const float4*)x, (float4*)y, n4);

    unsigned covered4 = n4 << 2;          // elements handled by vector kernel
    if (covered4 < n) {
        unsigned rem = n - covered4;
        unsigned tb = (rem + 255u) / 256u;
        ewise_sq_scalar_tail<<<tb, 256>>>(x, y, covered4, n);
    }
}

// round 14
// speedup vs baseline: 1.1011x; 1.1011x over previous
#include <cuda_runtime.h>
#include <cuda_bf16.h>
#include <cstdint>

// out = (((x+2)*3-5)/4)^2 = ((3x+1)/4)^2 ; t = fma(0.75, x, 0.25), out = t*t
// 64M fp32, pure HBM streaming. Measured ceiling on this GB300: ~6.45 TB/s
// (81% of spec) — invariant across unroll 2/4/8, 256/512-thread CTAs, and
// cache-hint variants; persistent grid-stride regresses (reduced chip-wide
// MLP). Final config: one-shot grid, 4x float4 per thread, front-batched
// .cg loads, .cs stores.

__global__ __launch_bounds__(256) void ewise_sq_kernel(
    const float4* __restrict__ in, float4* __restrict__ out, unsigned n4)
{
    const unsigned base = blockIdx.x * (256u * 4u) + threadIdx.x;
    const unsigned s = 256u;

    #define EW(dst, src) do {                       \
        float t0 = fmaf(0.75f, (src).x, 0.25f);     \
        float t1 = fmaf(0.75f, (src).y, 0.25f);     \
        float t2 = fmaf(0.75f, (src).z, 0.25f);     \
        float t3 = fmaf(0.75f, (src).w, 0.25f);     \
        (dst).x = t0 * t0; (dst).y = t1 * t1;       \
        (dst).z = t2 * t2; (dst).w = t3 * t3;       \
    } while (0)

    if (base + 3u * s < n4) {
        // Front-batch all 4 loads -> 4 outstanding LDG.128 per thread.
        float4 a0 = __ldcg(&in[base]);
        float4 a1 = __ldcg(&in[base + s]);
        float4 a2 = __ldcg(&in[base + 2u * s]);
        float4 a3 = __ldcg(&in[base + 3u * s]);

        float4 r0, r1, r2, r3;
        EW(r0, a0); EW(r1, a1); EW(r2, a2); EW(r3, a3);

        __stcs(&out[base],          r0);
        __stcs(&out[base + s],      r1);
        __stcs(&out[base + 2u * s], r2);
        __stcs(&out[base + 3u * s], r3);
    } else {
        for (unsigned k = 0; k < 4u; k++) {
            unsigned i = base + k * s;
            if (i < n4) {
                float4 a = __ldcg(&in[i]);
                float4 r;
                EW(r, a);
                __stcs(&out[i], r);
            }
        }
    }
    #undef EW
}

// Scalar tail for element counts not divisible by 4 (not hit for 8192x8192).
__global__ void ewise_sq_scalar_tail(const float* __restrict__ in,
                                     float* __restrict__ out,
                                     unsigned start, unsigned n)
{
    unsigned i = start + blockIdx.x * blockDim.x + threadIdx.x;
    if (i < n) {
        float t = fmaf(0.75f, in[i], 0.25f);
        out[i] = t * t;
    }
}

extern "C" void kernel_launch(void* const* d_in, const int* in_sizes, int n_in,
                              void* d_out, int out_size)
{
    const float* x = (const float*)d_in[0];
    float* y = (float*)d_out;
    unsigned n = (unsigned)in_sizes[0];   // 67108864
    unsigned n4 = n >> 2;                 // 16777216 float4

    const unsigned per_block = 256u * 4u;                 // 1024 float4 / block
    unsigned blocks = (n4 + per_block - 1u) / per_block;  // 16384 blocks

    ewise_sq_kernel<<<blocks, 256>>>((const float4*)x, (float4*)y, n4);

    unsigned covered4 = n4 << 2;
    if (covered4 < n) {
        unsigned rem = n - covered4;
        unsigned tb = (rem + 255u) / 256u;
        ewise_sq_scalar_tail<<<tb, 256>>>(x, y, covered4, n);
    }
}